// round 9
// baseline (speedup 1.0000x reference)
#include <cuda_runtime.h>
#include <cstdint>

#define BB   4
#define NN   2048
#define MM   2048
#define HH   16
#define DHH  64
#define IDD  1024
#define SCALE 0.125f
#define MAXNEG (-3.402823466e38f)

#define XSZ (BB * NN * IDD)   // 8388608
#define WSZ (IDD * IDD)       // 1048576

// scratch: Q/K/V/AO hold tf32 bits now
__device__ uint32_t g_Q[XSZ];
__device__ uint32_t g_K[XSZ];
__device__ uint32_t g_V[XSZ];
__device__ uint32_t g_AO[XSZ];
__device__ uint32_t g_xc[XSZ];
__device__ uint32_t g_cc[XSZ];
__device__ uint32_t g_wq[WSZ];
__device__ uint32_t g_wk[WSZ];
__device__ uint32_t g_wv[WSZ];
__device__ uint32_t g_wo[WSZ];

// ---------------------------------------------------------------------------
// helpers
// ---------------------------------------------------------------------------
__device__ __forceinline__ uint32_t f2t(float x) {
    uint32_t u;
    asm("cvt.rna.tf32.f32 %0, %1;" : "=r"(u) : "f"(x));
    return u;
}

__device__ __forceinline__ void mma8(float* c,
    uint32_t a0, uint32_t a1, uint32_t a2, uint32_t a3,
    uint32_t b0, uint32_t b1)
{
    asm volatile(
        "mma.sync.aligned.m16n8k8.row.col.f32.tf32.tf32.f32 "
        "{%0,%1,%2,%3}, {%4,%5,%6,%7}, {%8,%9}, {%0,%1,%2,%3};"
        : "+f"(c[0]), "+f"(c[1]), "+f"(c[2]), "+f"(c[3])
        : "r"(a0), "r"(a1), "r"(a2), "r"(a3), "r"(b0), "r"(b1));
}

__device__ __forceinline__ void ldsm4(uint32_t* r, uint32_t saddr) {
    asm volatile("ldmatrix.sync.aligned.m8n8.x4.shared.b16 {%0,%1,%2,%3}, [%4];"
        : "=r"(r[0]), "=r"(r[1]), "=r"(r[2]), "=r"(r[3]) : "r"(saddr));
}

__device__ __forceinline__ void cp16(uint32_t dst_smem, const void* src) {
    asm volatile("cp.async.cg.shared.global [%0], [%1], 16;"
        :: "r"(dst_smem), "l"(src));
}

// ---------------------------------------------------------------------------
// elementwise fp32 -> tf32 bits
// ---------------------------------------------------------------------------
__global__ __launch_bounds__(256) void cvt_tf32(
    const float* __restrict__ in, uint32_t* __restrict__ out, int n4)
{
    const int i = blockIdx.x * 256 + threadIdx.x;
    if (i < n4) {
        const float4 v = reinterpret_cast<const float4*>(in)[i];
        reinterpret_cast<uint4*>(out)[i] =
            make_uint4(f2t(v.x), f2t(v.y), f2t(v.z), f2t(v.w));
    }
}

// ---------------------------------------------------------------------------
// TF32 GEMM (pre-converted operands): C[8192x1024] = A @ W
// 128x128x32 tile, 256 threads, cp.async double-buffered.
// obits=1: write tf32 bits of (acc*oscale). obits=0: fp32 + bias.
// ---------------------------------------------------------------------------
#define ASP 36
#define BSP 136
#define A_WORDS (128 * ASP)
#define B_WORDS (32 * BSP)
#define GEMM_SMEM_BYTES (2 * (A_WORDS + B_WORDS) * 4)

__global__ __launch_bounds__(256) void gemm_tf32(
    const uint32_t* __restrict__ A, const uint32_t* __restrict__ W,
    const float* __restrict__ bias, void* __restrict__ Cv,
    int obits, float oscale)
{
    extern __shared__ uint32_t smg[];
    uint32_t* As = smg;
    uint32_t* Bs = smg + 2 * A_WORDS;

    const int tid  = threadIdx.x;
    const int lane = tid & 31;
    const int wid  = tid >> 5;
    const int g    = lane >> 2;
    const int tig  = lane & 3;
    const int wm   = wid & 1;
    const int wn   = wid >> 1;
    const int row0 = blockIdx.y * 128;
    const int col0 = blockIdx.x * 128;

    const int arow = lane & 15;
    const int acol = (lane >> 4) * 4;
    const uint32_t As_base = (uint32_t)__cvta_generic_to_shared(As);
    const uint32_t Bs_base = (uint32_t)__cvta_generic_to_shared(Bs);

    const int far = tid >> 3;
    const int fak = (tid & 7) * 4;
    const int fbk = tid >> 5;
    const int fbn = (tid & 31) * 4;

    float acc[4][4][4];
#pragma unroll
    for (int mi = 0; mi < 4; mi++)
#pragma unroll
        for (int ni = 0; ni < 4; ni++)
#pragma unroll
            for (int r = 0; r < 4; r++) acc[mi][ni][r] = 0.f;

    auto fill = [&](int s, int kt) {
        const uint32_t ab = As_base + s * A_WORDS * 4;
        const uint32_t bb = Bs_base + s * B_WORDS * 4;
#pragma unroll
        for (int i = 0; i < 4; i++) {
            const int r = far + i * 32;
            cp16(ab + (r * ASP + fak) * 4,
                 A + (size_t)(row0 + r) * 1024 + kt + fak);
        }
#pragma unroll
        for (int i = 0; i < 4; i++) {
            const int k = fbk + i * 8;
            cp16(bb + (k * BSP + fbn) * 4,
                 W + (size_t)(kt + k) * 1024 + col0 + fbn);
        }
        asm volatile("cp.async.commit_group;");
    };

    fill(0, 0);

    for (int t = 0; t < 32; t++) {
        const int cur = t & 1;
        if (t + 1 < 32) {
            fill(cur ^ 1, (t + 1) * 32);
            asm volatile("cp.async.wait_group 1;");
        } else {
            asm volatile("cp.async.wait_group 0;");
        }
        __syncthreads();

        const uint32_t ab = As_base + cur * A_WORDS * 4;
        const uint32_t* Bb = Bs + cur * B_WORDS;

#pragma unroll
        for (int kk = 0; kk < 32; kk += 8) {
            uint32_t af[4][4];
#pragma unroll
            for (int mi = 0; mi < 4; mi++) {
                const int m0 = wm * 64 + mi * 16;
                ldsm4(af[mi], ab + ((m0 + arow) * ASP + acol + kk) * 4);
            }
#pragma unroll
            for (int ni = 0; ni < 4; ni++) {
                const int n0 = wn * 32 + ni * 8;
                const uint32_t b0 = Bb[(kk + tig)     * BSP + n0 + g];
                const uint32_t b1 = Bb[(kk + tig + 4) * BSP + n0 + g];
#pragma unroll
                for (int mi = 0; mi < 4; mi++)
                    mma8(acc[mi][ni], af[mi][0], af[mi][1], af[mi][2], af[mi][3], b0, b1);
            }
        }
        __syncthreads();
    }

    if (obits) {
        uint32_t* Cb = (uint32_t*)Cv;
#pragma unroll
        for (int mi = 0; mi < 4; mi++) {
            const int rA = row0 + wm * 64 + mi * 16 + g;
#pragma unroll
            for (int ni = 0; ni < 4; ni++) {
                const int col = col0 + wn * 32 + ni * 8 + 2 * tig;
                *reinterpret_cast<uint2*>(&Cb[(size_t)rA * 1024 + col]) =
                    make_uint2(f2t(acc[mi][ni][0] * oscale), f2t(acc[mi][ni][1] * oscale));
                *reinterpret_cast<uint2*>(&Cb[(size_t)(rA + 8) * 1024 + col]) =
                    make_uint2(f2t(acc[mi][ni][2] * oscale), f2t(acc[mi][ni][3] * oscale));
            }
        }
    } else {
        float* Cf = (float*)Cv;
#pragma unroll
        for (int mi = 0; mi < 4; mi++) {
            const int rA = row0 + wm * 64 + mi * 16 + g;
#pragma unroll
            for (int ni = 0; ni < 4; ni++) {
                const int col = col0 + wn * 32 + ni * 8 + 2 * tig;
                const float b0v = bias[col], b1v = bias[col + 1];
                *reinterpret_cast<float2*>(&Cf[(size_t)rA * 1024 + col]) =
                    make_float2(acc[mi][ni][0] + b0v, acc[mi][ni][1] + b1v);
                *reinterpret_cast<float2*>(&Cf[(size_t)(rA + 8) * 1024 + col]) =
                    make_float2(acc[mi][ni][2] + b0v, acc[mi][ni][3] + b1v);
            }
        }
    }
}

// ---------------------------------------------------------------------------
// TF32 flash attention: CTA = 256 queries, 8 warps x 32 rows. 64-key chunks,
// cp.async double-buffered K/V (inputs are pre-converted tf32 bits).
// ---------------------------------------------------------------------------
#define QSP 68
#define KVW (64 * QSP)   // words per K or V chunk buffer
#define ATT_SMEM_BYTES ((256 * QSP + 2 * KVW + 2 * KVW + 256 * QSP) * 4 + 768)

__global__ __launch_bounds__(256) void attn_tc(
    const uint32_t* __restrict__ Q, const uint32_t* __restrict__ K,
    const uint32_t* __restrict__ V, const int* __restrict__ mask,
    uint32_t* __restrict__ AO)
{
    extern __shared__ uint32_t sm[];
    uint32_t* Qs = sm;                    // [256][QSP]
    uint32_t* Ks = Qs + 256 * QSP;        // [2][64][QSP]
    uint32_t* Vs = Ks + 2 * KVW;          // [2][64][QSP]
    uint32_t* Ss = Vs + 2 * KVW;          // [256][QSP]
    int*      msk = (int*)(Ss + 256 * QSP);   // [2][64]

    const int tid  = threadIdx.x;
    const int lane = tid & 31;
    const int wid  = tid >> 5;
    const int g    = lane >> 2;
    const int tig  = lane & 3;
    const int n0   = blockIdx.x * 256;
    const int h    = blockIdx.y;
    const int b    = blockIdx.z;
    const int q0   = wid * 32;

    const int arow = lane & 15;
    const int acol = (lane >> 4) * 4;
    const int krow = (lane & 7) + ((lane >> 4) << 3);
    const int kcol = (lane & 8) ? 4 : 0;
    const uint32_t Qs_b = (uint32_t)__cvta_generic_to_shared(Qs);
    const uint32_t Ks_b = (uint32_t)__cvta_generic_to_shared(Ks);
    const uint32_t Vs_b = (uint32_t)__cvta_generic_to_shared(Vs);
    const uint32_t Ss_b = (uint32_t)__cvta_generic_to_shared(Ss);

    const int fr  = tid >> 4;     // K/V fill row base
    const int fd4 = (tid & 15) * 4;

    // async K/V chunk fill (raw bit copy, no cvt)
    auto fillKV = [&](int j0, int s) {
        const uint32_t kb = Ks_b + s * KVW * 4;
        const uint32_t vb = Vs_b + s * KVW * 4;
#pragma unroll
        for (int i = 0; i < 4; i++) {
            const int r = fr + i * 16;
            const size_t gb = ((size_t)b * MM + j0 + r) * IDD + h * 64 + fd4;
            cp16(kb + (r * QSP + fd4) * 4, K + gb);
            cp16(vb + (r * QSP + fd4) * 4, V + gb);
        }
        asm volatile("cp.async.commit_group;");
    };

    // prologue: Q (async, once) + chunk 0 + mask 0
#pragma unroll
    for (int i = 0; i < 16; i++) {
        const int r = fr + i * 16;
        cp16(Qs_b + (r * QSP + fd4) * 4,
             Q + ((size_t)b * NN + n0 + r) * IDD + h * 64 + fd4);
    }
    if (tid < 64) msk[tid] = mask[(size_t)b * MM + tid];
    fillKV(0, 0);

    float o[2][8][4];
#pragma unroll
    for (int t = 0; t < 2; t++)
#pragma unroll
        for (int nf = 0; nf < 8; nf++)
#pragma unroll
            for (int r = 0; r < 4; r++) o[t][nf][r] = 0.f;
    float mr[2][2], lr[2][2];
#pragma unroll
    for (int t = 0; t < 2; t++) {
        mr[t][0] = MAXNEG; mr[t][1] = MAXNEG;
        lr[t][0] = 0.f;    lr[t][1] = 0.f;
    }

    for (int it = 0; it < 32; it++) {
        const int cur = it & 1;
        if (it + 1 < 32) {
            fillKV((it + 1) * 64, cur ^ 1);
            if (tid < 64)
                msk[(cur ^ 1) * 64 + tid] = mask[(size_t)b * MM + (it + 1) * 64 + tid];
            asm volatile("cp.async.wait_group 1;");
        } else {
            asm volatile("cp.async.wait_group 0;");
        }
        __syncthreads();   // chunk `it` data + mask visible to all

        const uint32_t kbb = Ks_b + cur * KVW * 4;
        const uint32_t* Vb = Vs + cur * KVW;
        const int* mk = msk + cur * 64;

        // ---- S = Q @ K^T ----
        float s[2][8][4];
#pragma unroll
        for (int t = 0; t < 2; t++)
#pragma unroll
            for (int nf = 0; nf < 8; nf++)
#pragma unroll
                for (int r = 0; r < 4; r++) s[t][nf][r] = 0.f;

#pragma unroll
        for (int ks = 0; ks < 8; ks++) {
            const int d0 = ks * 8;
            uint32_t qa[2][4];
            ldsm4(qa[0], Qs_b + ((q0 + arow)      * QSP + acol + d0) * 4);
            ldsm4(qa[1], Qs_b + ((q0 + 16 + arow) * QSP + acol + d0) * 4);
#pragma unroll
            for (int np = 0; np < 4; np++) {
                const int jc = np * 16;
                uint32_t kb[4];
                ldsm4(kb, kbb + ((jc + krow) * QSP + kcol + d0) * 4);
                mma8(s[0][2*np],   qa[0][0], qa[0][1], qa[0][2], qa[0][3], kb[0], kb[1]);
                mma8(s[0][2*np+1], qa[0][0], qa[0][1], qa[0][2], qa[0][3], kb[2], kb[3]);
                mma8(s[1][2*np],   qa[1][0], qa[1][1], qa[1][2], qa[1][3], kb[0], kb[1]);
                mma8(s[1][2*np+1], qa[1][0], qa[1][1], qa[1][2], qa[1][3], kb[2], kb[3]);
            }
        }

        // ---- mask + online softmax + P->smem ----
#pragma unroll
        for (int t = 0; t < 2; t++) {
            float cmA = MAXNEG, cmB = MAXNEG;
#pragma unroll
            for (int nf = 0; nf < 8; nf++) {
                const int c0 = nf * 8 + 2 * tig;
                if (!mk[c0])     { s[t][nf][0] = MAXNEG; s[t][nf][2] = MAXNEG; }
                if (!mk[c0 + 1]) { s[t][nf][1] = MAXNEG; s[t][nf][3] = MAXNEG; }
                cmA = fmaxf(cmA, fmaxf(s[t][nf][0], s[t][nf][1]));
                cmB = fmaxf(cmB, fmaxf(s[t][nf][2], s[t][nf][3]));
            }
            cmA = fmaxf(cmA, __shfl_xor_sync(0xffffffffu, cmA, 1));
            cmA = fmaxf(cmA, __shfl_xor_sync(0xffffffffu, cmA, 2));
            cmB = fmaxf(cmB, __shfl_xor_sync(0xffffffffu, cmB, 1));
            cmB = fmaxf(cmB, __shfl_xor_sync(0xffffffffu, cmB, 2));

            const float mnA = fmaxf(mr[t][0], cmA);
            const float mnB = fmaxf(mr[t][1], cmB);
            const float alA = __expf(mr[t][0] - mnA);
            const float alB = __expf(mr[t][1] - mnB);
            mr[t][0] = mnA; mr[t][1] = mnB;

            float suA = 0.f, suB = 0.f;
            const int rA = q0 + t * 16 + g;
#pragma unroll
            for (int nf = 0; nf < 8; nf++) {
                const float p0 = __expf(s[t][nf][0] - mnA);
                const float p1 = __expf(s[t][nf][1] - mnA);
                const float p2 = __expf(s[t][nf][2] - mnB);
                const float p3 = __expf(s[t][nf][3] - mnB);
                suA += p0 + p1;
                suB += p2 + p3;
                const int c0 = nf * 8 + 2 * tig;
                *reinterpret_cast<uint2*>(&Ss[rA       * QSP + c0]) =
                    make_uint2(f2t(p0), f2t(p1));
                *reinterpret_cast<uint2*>(&Ss[(rA + 8) * QSP + c0]) =
                    make_uint2(f2t(p2), f2t(p3));
            }
            suA += __shfl_xor_sync(0xffffffffu, suA, 1);
            suA += __shfl_xor_sync(0xffffffffu, suA, 2);
            suB += __shfl_xor_sync(0xffffffffu, suB, 1);
            suB += __shfl_xor_sync(0xffffffffu, suB, 2);
            lr[t][0] = lr[t][0] * alA + suA;
            lr[t][1] = lr[t][1] * alB + suB;

#pragma unroll
            for (int nf = 0; nf < 8; nf++) {
                o[t][nf][0] *= alA; o[t][nf][1] *= alA;
                o[t][nf][2] *= alB; o[t][nf][3] *= alB;
            }
        }
        __syncwarp();

        // ---- O += P @ V ----
#pragma unroll
        for (int ks = 0; ks < 8; ks++) {
            const int s0 = ks * 8;
            uint32_t pa[2][4];
            ldsm4(pa[0], Ss_b + ((q0 + arow)      * QSP + acol + s0) * 4);
            ldsm4(pa[1], Ss_b + ((q0 + 16 + arow) * QSP + acol + s0) * 4);
#pragma unroll
            for (int nf = 0; nf < 8; nf++) {
                const int d0 = nf * 8;
                const uint32_t b0 = Vb[(s0 + tig)     * QSP + d0 + g];
                const uint32_t b1 = Vb[(s0 + tig + 4) * QSP + d0 + g];
                mma8(o[0][nf], pa[0][0], pa[0][1], pa[0][2], pa[0][3], b0, b1);
                mma8(o[1][nf], pa[1][0], pa[1][1], pa[1][2], pa[1][3], b0, b1);
            }
        }
        __syncthreads();   // done with buf `cur` before it+2 prefetch overwrites
    }

    // normalize + write tf32 bits
#pragma unroll
    for (int t = 0; t < 2; t++) {
        const float liA = 1.f / lr[t][0];
        const float liB = 1.f / lr[t][1];
        const int rq = q0 + t * 16 + g;
#pragma unroll
        for (int nf = 0; nf < 8; nf++) {
            const int col = h * 64 + nf * 8 + 2 * tig;
            const size_t rA = ((size_t)b * NN + n0 + rq)     * IDD + col;
            const size_t rB = ((size_t)b * NN + n0 + rq + 8) * IDD + col;
            *reinterpret_cast<uint2*>(&AO[rA]) =
                make_uint2(f2t(o[t][nf][0] * liA), f2t(o[t][nf][1] * liA));
            *reinterpret_cast<uint2*>(&AO[rB]) =
                make_uint2(f2t(o[t][nf][2] * liB), f2t(o[t][nf][3] * liB));
        }
    }
}

// ---------------------------------------------------------------------------
// Launch
// ---------------------------------------------------------------------------
extern "C" void kernel_launch(void* const* d_in, const int* in_sizes, int n_in,
                              void* d_out, int out_size)
{
    const float* x    = (const float*)d_in[0];
    const float* ctx  = (const float*)d_in[1];
    const int*   mask = (const int*)d_in[2];
    const float* Wq   = (const float*)d_in[3];
    const float* Wk   = (const float*)d_in[4];
    const float* Wv   = (const float*)d_in[5];
    const float* Wo   = (const float*)d_in[6];
    const float* bo   = (const float*)d_in[7];
    float* out        = (float*)d_out;

    uint32_t *Qp, *Kp, *Vp, *AOp, *xc, *cc, *wq, *wk, *wv, *wo;
    cudaGetSymbolAddress((void**)&Qp,  g_Q);
    cudaGetSymbolAddress((void**)&Kp,  g_K);
    cudaGetSymbolAddress((void**)&Vp,  g_V);
    cudaGetSymbolAddress((void**)&AOp, g_AO);
    cudaGetSymbolAddress((void**)&xc,  g_xc);
    cudaGetSymbolAddress((void**)&cc,  g_cc);
    cudaGetSymbolAddress((void**)&wq,  g_wq);
    cudaGetSymbolAddress((void**)&wk,  g_wk);
    cudaGetSymbolAddress((void**)&wv,  g_wv);
    cudaGetSymbolAddress((void**)&wo,  g_wo);

    cudaFuncSetAttribute(attn_tc,
                         cudaFuncAttributeMaxDynamicSharedMemorySize,
                         ATT_SMEM_BYTES);
    cudaFuncSetAttribute(gemm_tf32,
                         cudaFuncAttributeMaxDynamicSharedMemorySize,
                         GEMM_SMEM_BYTES);

    cvt_tf32<<<XSZ / 4 / 256, 256>>>(x,   xc, XSZ / 4);
    cvt_tf32<<<XSZ / 4 / 256, 256>>>(ctx, cc, XSZ / 4);
    cvt_tf32<<<WSZ / 4 / 256, 256>>>(Wq,  wq, WSZ / 4);
    cvt_tf32<<<WSZ / 4 / 256, 256>>>(Wk,  wk, WSZ / 4);
    cvt_tf32<<<WSZ / 4 / 256, 256>>>(Wv,  wv, WSZ / 4);
    cvt_tf32<<<WSZ / 4 / 256, 256>>>(Wo,  wo, WSZ / 4);

    const dim3 gg(1024 / 128, (BB * NN) / 128);   // (8, 64)
    const dim3 bk(256);

    gemm_tf32<<<gg, bk, GEMM_SMEM_BYTES>>>(xc, wq, nullptr, Qp, 1, SCALE);
    gemm_tf32<<<gg, bk, GEMM_SMEM_BYTES>>>(cc, wk, nullptr, Kp, 1, 1.0f);
    gemm_tf32<<<gg, bk, GEMM_SMEM_BYTES>>>(cc, wv, nullptr, Vp, 1, 1.0f);

    attn_tc<<<dim3(NN / 256, HH, BB), 256, ATT_SMEM_BYTES>>>(
        Qp, Kp, Vp, mask, AOp);

    gemm_tf32<<<gg, bk, GEMM_SMEM_BYTES>>>(AOp, wo, bo, out, 0, 1.0f);
}

// round 10
// speedup vs baseline: 1.2119x; 1.2119x over previous
#include <cuda_runtime.h>
#include <cstdint>

#define BB   4
#define NN   2048
#define MM   2048
#define HH   16
#define DHH  64
#define IDD  1024
#define SCALE 0.125f
#define MAXNEG (-3.402823466e38f)

#define XSZ (BB * NN * IDD)
#define WSZ (IDD * IDD)

__device__ uint32_t g_Q[XSZ];
__device__ uint32_t g_K[XSZ];
__device__ uint32_t g_V[XSZ];
__device__ uint32_t g_AO[XSZ];
__device__ uint32_t g_xc[XSZ];
__device__ uint32_t g_cc[XSZ];
__device__ uint32_t g_wq[WSZ];
__device__ uint32_t g_wk[WSZ];
__device__ uint32_t g_wv[WSZ];
__device__ uint32_t g_wo[WSZ];

// ---------------------------------------------------------------------------
__device__ __forceinline__ uint32_t f2t(float x) {
    uint32_t u;
    asm("cvt.rna.tf32.f32 %0, %1;" : "=r"(u) : "f"(x));
    return u;
}

__device__ __forceinline__ void mma8(float* c,
    uint32_t a0, uint32_t a1, uint32_t a2, uint32_t a3,
    uint32_t b0, uint32_t b1)
{
    asm volatile(
        "mma.sync.aligned.m16n8k8.row.col.f32.tf32.tf32.f32 "
        "{%0,%1,%2,%3}, {%4,%5,%6,%7}, {%8,%9}, {%0,%1,%2,%3};"
        : "+f"(c[0]), "+f"(c[1]), "+f"(c[2]), "+f"(c[3])
        : "r"(a0), "r"(a1), "r"(a2), "r"(a3), "r"(b0), "r"(b1));
}

__device__ __forceinline__ void ldsm4(uint32_t* r, uint32_t saddr) {
    asm volatile("ldmatrix.sync.aligned.m8n8.x4.shared.b16 {%0,%1,%2,%3}, [%4];"
        : "=r"(r[0]), "=r"(r[1]), "=r"(r[2]), "=r"(r[3]) : "r"(saddr));
}

__device__ __forceinline__ void cp16(uint32_t dst_smem, const void* src) {
    asm volatile("cp.async.cg.shared.global [%0], [%1], 16;"
        :: "r"(dst_smem), "l"(src));
}

// ---------------------------------------------------------------------------
__global__ __launch_bounds__(256) void cvt_tf32(
    const float* __restrict__ in, uint32_t* __restrict__ out, int n4)
{
    const int i = blockIdx.x * 256 + threadIdx.x;
    if (i < n4) {
        const float4 v = reinterpret_cast<const float4*>(in)[i];
        reinterpret_cast<uint4*>(out)[i] =
            make_uint4(f2t(v.x), f2t(v.y), f2t(v.z), f2t(v.w));
    }
}

// ---------------------------------------------------------------------------
// TF32 GEMM (pre-converted operands) — unchanged from R9
// ---------------------------------------------------------------------------
#define ASP 36
#define BSP 136
#define A_WORDS (128 * ASP)
#define B_WORDS (32 * BSP)
#define GEMM_SMEM_BYTES (2 * (A_WORDS + B_WORDS) * 4)

__global__ __launch_bounds__(256) void gemm_tf32(
    const uint32_t* __restrict__ A, const uint32_t* __restrict__ W,
    const float* __restrict__ bias, void* __restrict__ Cv,
    int obits, float oscale)
{
    extern __shared__ uint32_t smg[];
    uint32_t* As = smg;
    uint32_t* Bs = smg + 2 * A_WORDS;

    const int tid  = threadIdx.x;
    const int lane = tid & 31;
    const int wid  = tid >> 5;
    const int g    = lane >> 2;
    const int tig  = lane & 3;
    const int wm   = wid & 1;
    const int wn   = wid >> 1;
    const int row0 = blockIdx.y * 128;
    const int col0 = blockIdx.x * 128;

    const int arow = lane & 15;
    const int acol = (lane >> 4) * 4;
    const uint32_t As_base = (uint32_t)__cvta_generic_to_shared(As);
    const uint32_t Bs_base = (uint32_t)__cvta_generic_to_shared(Bs);

    const int far = tid >> 3;
    const int fak = (tid & 7) * 4;
    const int fbk = tid >> 5;
    const int fbn = (tid & 31) * 4;

    float acc[4][4][4];
#pragma unroll
    for (int mi = 0; mi < 4; mi++)
#pragma unroll
        for (int ni = 0; ni < 4; ni++)
#pragma unroll
            for (int r = 0; r < 4; r++) acc[mi][ni][r] = 0.f;

    auto fill = [&](int s, int kt) {
        const uint32_t ab = As_base + s * A_WORDS * 4;
        const uint32_t bb = Bs_base + s * B_WORDS * 4;
#pragma unroll
        for (int i = 0; i < 4; i++) {
            const int r = far + i * 32;
            cp16(ab + (r * ASP + fak) * 4,
                 A + (size_t)(row0 + r) * 1024 + kt + fak);
        }
#pragma unroll
        for (int i = 0; i < 4; i++) {
            const int k = fbk + i * 8;
            cp16(bb + (k * BSP + fbn) * 4,
                 W + (size_t)(kt + k) * 1024 + col0 + fbn);
        }
        asm volatile("cp.async.commit_group;");
    };

    fill(0, 0);

    for (int t = 0; t < 32; t++) {
        const int cur = t & 1;
        if (t + 1 < 32) {
            fill(cur ^ 1, (t + 1) * 32);
            asm volatile("cp.async.wait_group 1;");
        } else {
            asm volatile("cp.async.wait_group 0;");
        }
        __syncthreads();

        const uint32_t ab = As_base + cur * A_WORDS * 4;
        const uint32_t* Bb = Bs + cur * B_WORDS;

#pragma unroll
        for (int kk = 0; kk < 32; kk += 8) {
            uint32_t af[4][4];
#pragma unroll
            for (int mi = 0; mi < 4; mi++) {
                const int m0 = wm * 64 + mi * 16;
                ldsm4(af[mi], ab + ((m0 + arow) * ASP + acol + kk) * 4);
            }
#pragma unroll
            for (int ni = 0; ni < 4; ni++) {
                const int n0 = wn * 32 + ni * 8;
                const uint32_t b0 = Bb[(kk + tig)     * BSP + n0 + g];
                const uint32_t b1 = Bb[(kk + tig + 4) * BSP + n0 + g];
#pragma unroll
                for (int mi = 0; mi < 4; mi++)
                    mma8(acc[mi][ni], af[mi][0], af[mi][1], af[mi][2], af[mi][3], b0, b1);
            }
        }
        __syncthreads();
    }

    if (obits) {
        uint32_t* Cb = (uint32_t*)Cv;
#pragma unroll
        for (int mi = 0; mi < 4; mi++) {
            const int rA = row0 + wm * 64 + mi * 16 + g;
#pragma unroll
            for (int ni = 0; ni < 4; ni++) {
                const int col = col0 + wn * 32 + ni * 8 + 2 * tig;
                *reinterpret_cast<uint2*>(&Cb[(size_t)rA * 1024 + col]) =
                    make_uint2(f2t(acc[mi][ni][0] * oscale), f2t(acc[mi][ni][1] * oscale));
                *reinterpret_cast<uint2*>(&Cb[(size_t)(rA + 8) * 1024 + col]) =
                    make_uint2(f2t(acc[mi][ni][2] * oscale), f2t(acc[mi][ni][3] * oscale));
            }
        }
    } else {
        float* Cf = (float*)Cv;
#pragma unroll
        for (int mi = 0; mi < 4; mi++) {
            const int rA = row0 + wm * 64 + mi * 16 + g;
#pragma unroll
            for (int ni = 0; ni < 4; ni++) {
                const int col = col0 + wn * 32 + ni * 8 + 2 * tig;
                const float b0v = bias[col], b1v = bias[col + 1];
                *reinterpret_cast<float2*>(&Cf[(size_t)rA * 1024 + col]) =
                    make_float2(acc[mi][ni][0] + b0v, acc[mi][ni][1] + b1v);
                *reinterpret_cast<float2*>(&Cf[(size_t)(rA + 8) * 1024 + col]) =
                    make_float2(acc[mi][ni][2] + b0v, acc[mi][ni][3] + b1v);
            }
        }
    }
}

// ---------------------------------------------------------------------------
// TF32 flash attention, no-Ss variant:
// CTA = 128 queries, 8 warps x 16 rows. P stays in registers via key
// permutation sigma=(0,2,4,6,1,3,5,7) applied to V row addressing.
// Double-buffered K/V via cp.async. 2 CTAs/SM.
// ---------------------------------------------------------------------------
#define QSP 68
#define KVW (64 * QSP)
#define ATT_SMEM_BYTES ((128 * QSP + 4 * KVW) * 4 + 768)

__global__ __launch_bounds__(256, 2) void attn_tc(
    const uint32_t* __restrict__ Q, const uint32_t* __restrict__ K,
    const uint32_t* __restrict__ V, const int* __restrict__ mask,
    uint32_t* __restrict__ AO)
{
    extern __shared__ uint32_t sm[];
    uint32_t* Qs = sm;                    // [128][QSP]
    uint32_t* Ks = Qs + 128 * QSP;        // [2][64][QSP]
    uint32_t* Vs = Ks + 2 * KVW;          // [2][64][QSP]
    int*      msk = (int*)(Vs + 2 * KVW); // [2][64]

    const int tid  = threadIdx.x;
    const int lane = tid & 31;
    const int wid  = tid >> 5;
    const int g    = lane >> 2;
    const int tig  = lane & 3;
    const int n0   = blockIdx.x * 128;
    const int h    = blockIdx.y;
    const int b    = blockIdx.z;
    const int q0   = wid * 16;

    const int arow = lane & 15;
    const int acol = (lane >> 4) * 4;
    const int krow = (lane & 7) + ((lane >> 4) << 3);
    const int kcol = (lane & 8) ? 4 : 0;
    const uint32_t Qs_b = (uint32_t)__cvta_generic_to_shared(Qs);
    const uint32_t Ks_b = (uint32_t)__cvta_generic_to_shared(Ks);
    const uint32_t Vs_b = (uint32_t)__cvta_generic_to_shared(Vs);

    const int fr  = tid >> 4;
    const int fd4 = (tid & 15) * 4;

    auto fillKV = [&](int j0, int s) {
        const uint32_t kb = Ks_b + s * KVW * 4;
        const uint32_t vb = Vs_b + s * KVW * 4;
#pragma unroll
        for (int i = 0; i < 4; i++) {
            const int r = fr + i * 16;
            const size_t gb = ((size_t)b * MM + j0 + r) * IDD + h * 64 + fd4;
            cp16(kb + (r * QSP + fd4) * 4, K + gb);
            cp16(vb + (r * QSP + fd4) * 4, V + gb);
        }
        asm volatile("cp.async.commit_group;");
    };

    // prologue: Q (128 rows) + chunk 0 + mask 0 in one group
#pragma unroll
    for (int i = 0; i < 8; i++) {
        const int r = fr + i * 16;
        cp16(Qs_b + (r * QSP + fd4) * 4,
             Q + ((size_t)b * NN + n0 + r) * IDD + h * 64 + fd4);
    }
    if (tid < 64) msk[tid] = mask[(size_t)b * MM + tid];
    fillKV(0, 0);

    float o[8][4];
#pragma unroll
    for (int nf = 0; nf < 8; nf++)
#pragma unroll
        for (int r = 0; r < 4; r++) o[nf][r] = 0.f;
    float mA = MAXNEG, mB = MAXNEG, lA = 0.f, lB = 0.f;

    for (int it = 0; it < 32; it++) {
        const int cur = it & 1;
        if (it + 1 < 32) {
            fillKV((it + 1) * 64, cur ^ 1);
            if (tid < 64)
                msk[(cur ^ 1) * 64 + tid] = mask[(size_t)b * MM + (it + 1) * 64 + tid];
            asm volatile("cp.async.wait_group 1;");
        } else {
            asm volatile("cp.async.wait_group 0;");
        }
        __syncthreads();

        const uint32_t kbb = Ks_b + cur * KVW * 4;
        const uint32_t* Vb = Vs + cur * KVW;
        const int* mk = msk + cur * 64;

        // ---- S = Q @ K^T ----
        float s[8][4];
#pragma unroll
        for (int nf = 0; nf < 8; nf++)
#pragma unroll
            for (int r = 0; r < 4; r++) s[nf][r] = 0.f;

#pragma unroll
        for (int ks = 0; ks < 8; ks++) {
            const int d0 = ks * 8;
            uint32_t qa[4];
            ldsm4(qa, Qs_b + ((q0 + arow) * QSP + acol + d0) * 4);
#pragma unroll
            for (int np = 0; np < 4; np++) {
                const int jc = np * 16;
                uint32_t kb[4];
                ldsm4(kb, kbb + ((jc + krow) * QSP + kcol + d0) * 4);
                mma8(s[2*np],   qa[0], qa[1], qa[2], qa[3], kb[0], kb[1]);
                mma8(s[2*np+1], qa[0], qa[1], qa[2], qa[3], kb[2], kb[3]);
            }
        }

        // ---- mask + online softmax (P stays in s regs) ----
        float cmA = MAXNEG, cmB = MAXNEG;
#pragma unroll
        for (int nf = 0; nf < 8; nf++) {
            const int c0 = nf * 8 + 2 * tig;
            if (!mk[c0])     { s[nf][0] = MAXNEG; s[nf][2] = MAXNEG; }
            if (!mk[c0 + 1]) { s[nf][1] = MAXNEG; s[nf][3] = MAXNEG; }
            cmA = fmaxf(cmA, fmaxf(s[nf][0], s[nf][1]));
            cmB = fmaxf(cmB, fmaxf(s[nf][2], s[nf][3]));
        }
        cmA = fmaxf(cmA, __shfl_xor_sync(0xffffffffu, cmA, 1));
        cmA = fmaxf(cmA, __shfl_xor_sync(0xffffffffu, cmA, 2));
        cmB = fmaxf(cmB, __shfl_xor_sync(0xffffffffu, cmB, 1));
        cmB = fmaxf(cmB, __shfl_xor_sync(0xffffffffu, cmB, 2));

        const float mnA = fmaxf(mA, cmA);
        const float mnB = fmaxf(mB, cmB);
        const float alA = __expf(mA - mnA);
        const float alB = __expf(mB - mnB);
        mA = mnA; mB = mnB;

        float suA = 0.f, suB = 0.f;
#pragma unroll
        for (int nf = 0; nf < 8; nf++) {
            s[nf][0] = __expf(s[nf][0] - mnA);
            s[nf][1] = __expf(s[nf][1] - mnA);
            s[nf][2] = __expf(s[nf][2] - mnB);
            s[nf][3] = __expf(s[nf][3] - mnB);
            suA += s[nf][0] + s[nf][1];
            suB += s[nf][2] + s[nf][3];
        }
        suA += __shfl_xor_sync(0xffffffffu, suA, 1);
        suA += __shfl_xor_sync(0xffffffffu, suA, 2);
        suB += __shfl_xor_sync(0xffffffffu, suB, 1);
        suB += __shfl_xor_sync(0xffffffffu, suB, 2);
        lA = lA * alA + suA;
        lB = lB * alB + suB;

#pragma unroll
        for (int nf = 0; nf < 8; nf++) {
            o[nf][0] *= alA; o[nf][1] *= alA;
            o[nf][2] *= alB; o[nf][3] *= alB;
        }

        // ---- O += P @ V with sigma=(0,2,4,6,1,3,5,7) key permutation ----
        // A-frag (logical k-col tig -> key 2tig, tig+4 -> key 2tig+1):
        //   a0 = P[g][2tig] = s[ks][0], a1 = P[g+8][2tig] = s[ks][2],
        //   a2 = P[g][2tig+1] = s[ks][1], a3 = P[g+8][2tig+1] = s[ks][3]
        // B-frag rows: V[2tig], V[2tig+1]  (conflict-free: 8*tig+g banks)
#pragma unroll
        for (int ks = 0; ks < 8; ks++) {
            const int s0 = ks * 8;
            const uint32_t pa0 = f2t(s[ks][0]);
            const uint32_t pa1 = f2t(s[ks][2]);
            const uint32_t pa2 = f2t(s[ks][1]);
            const uint32_t pa3 = f2t(s[ks][3]);
#pragma unroll
            for (int nf = 0; nf < 8; nf++) {
                const int d0 = nf * 8;
                const uint32_t b0 = Vb[(s0 + 2 * tig)     * QSP + d0 + g];
                const uint32_t b1 = Vb[(s0 + 2 * tig + 1) * QSP + d0 + g];
                mma8(o[nf], pa0, pa1, pa2, pa3, b0, b1);
            }
        }
        __syncthreads();   // done with buf `cur` before it+2 prefetch overwrites
    }

    // normalize + write tf32 bits
    const float liA = 1.f / lA;
    const float liB = 1.f / lB;
#pragma unroll
    for (int nf = 0; nf < 8; nf++) {
        const int col = h * 64 + nf * 8 + 2 * tig;
        const size_t rA = ((size_t)b * NN + n0 + q0 + g)     * IDD + col;
        const size_t rB = ((size_t)b * NN + n0 + q0 + g + 8) * IDD + col;
        *reinterpret_cast<uint2*>(&AO[rA]) =
            make_uint2(f2t(o[nf][0] * liA), f2t(o[nf][1] * liA));
        *reinterpret_cast<uint2*>(&AO[rB]) =
            make_uint2(f2t(o[nf][2] * liB), f2t(o[nf][3] * liB));
    }
}

// ---------------------------------------------------------------------------
// Launch
// ---------------------------------------------------------------------------
extern "C" void kernel_launch(void* const* d_in, const int* in_sizes, int n_in,
                              void* d_out, int out_size)
{
    const float* x    = (const float*)d_in[0];
    const float* ctx  = (const float*)d_in[1];
    const int*   mask = (const int*)d_in[2];
    const float* Wq   = (const float*)d_in[3];
    const float* Wk   = (const float*)d_in[4];
    const float* Wv   = (const float*)d_in[5];
    const float* Wo   = (const float*)d_in[6];
    const float* bo   = (const float*)d_in[7];
    float* out        = (float*)d_out;

    uint32_t *Qp, *Kp, *Vp, *AOp, *xc, *cc, *wq, *wk, *wv, *wo;
    cudaGetSymbolAddress((void**)&Qp,  g_Q);
    cudaGetSymbolAddress((void**)&Kp,  g_K);
    cudaGetSymbolAddress((void**)&Vp,  g_V);
    cudaGetSymbolAddress((void**)&AOp, g_AO);
    cudaGetSymbolAddress((void**)&xc,  g_xc);
    cudaGetSymbolAddress((void**)&cc,  g_cc);
    cudaGetSymbolAddress((void**)&wq,  g_wq);
    cudaGetSymbolAddress((void**)&wk,  g_wk);
    cudaGetSymbolAddress((void**)&wv,  g_wv);
    cudaGetSymbolAddress((void**)&wo,  g_wo);

    cudaFuncSetAttribute(attn_tc,
                         cudaFuncAttributeMaxDynamicSharedMemorySize,
                         ATT_SMEM_BYTES);
    cudaFuncSetAttribute(gemm_tf32,
                         cudaFuncAttributeMaxDynamicSharedMemorySize,
                         GEMM_SMEM_BYTES);

    cvt_tf32<<<XSZ / 4 / 256, 256>>>(x,   xc, XSZ / 4);
    cvt_tf32<<<XSZ / 4 / 256, 256>>>(ctx, cc, XSZ / 4);
    cvt_tf32<<<WSZ / 4 / 256, 256>>>(Wq,  wq, WSZ / 4);
    cvt_tf32<<<WSZ / 4 / 256, 256>>>(Wk,  wk, WSZ / 4);
    cvt_tf32<<<WSZ / 4 / 256, 256>>>(Wv,  wv, WSZ / 4);
    cvt_tf32<<<WSZ / 4 / 256, 256>>>(Wo,  wo, WSZ / 4);

    const dim3 gg(1024 / 128, (BB * NN) / 128);   // (8, 64)
    const dim3 bk(256);

    gemm_tf32<<<gg, bk, GEMM_SMEM_BYTES>>>(xc, wq, nullptr, Qp, 1, SCALE);
    gemm_tf32<<<gg, bk, GEMM_SMEM_BYTES>>>(cc, wk, nullptr, Kp, 1, 1.0f);
    gemm_tf32<<<gg, bk, GEMM_SMEM_BYTES>>>(cc, wv, nullptr, Vp, 1, 1.0f);

    attn_tc<<<dim3(NN / 128, HH, BB), 256, ATT_SMEM_BYTES>>>(
        Qp, Kp, Vp, mask, AOp);

    gemm_tf32<<<gg, bk, GEMM_SMEM_BYTES>>>(AOp, wo, bo, out, 0, 1.0f);
}

// round 13
// speedup vs baseline: 1.2677x; 1.0461x over previous
#include <cuda_runtime.h>
#include <cstdint>

#define BB   4
#define NN   2048
#define MM   2048
#define HH   16
#define DHH  64
#define IDD  1024
#define SCALE 0.125f
#define MAXNEG (-3.402823466e38f)

#define XSZ (BB * NN * IDD)
#define WSZ (IDD * IDD)

__device__ uint32_t g_Q[XSZ];
__device__ uint32_t g_K[XSZ];
__device__ uint32_t g_V[XSZ];
__device__ uint32_t g_AO[XSZ];
__device__ uint32_t g_xc[XSZ];
__device__ uint32_t g_cc[XSZ];
__device__ uint32_t g_wq[WSZ];
__device__ uint32_t g_wk[WSZ];
__device__ uint32_t g_wv[WSZ];
__device__ uint32_t g_wo[WSZ];

// ---------------------------------------------------------------------------
__device__ __forceinline__ uint32_t f2t(float x) {
    uint32_t u;
    asm("cvt.rna.tf32.f32 %0, %1;" : "=r"(u) : "f"(x));
    return u;
}

__device__ __forceinline__ void mma8(float* c,
    uint32_t a0, uint32_t a1, uint32_t a2, uint32_t a3,
    uint32_t b0, uint32_t b1)
{
    asm volatile(
        "mma.sync.aligned.m16n8k8.row.col.f32.tf32.tf32.f32 "
        "{%0,%1,%2,%3}, {%4,%5,%6,%7}, {%8,%9}, {%0,%1,%2,%3};"
        : "+f"(c[0]), "+f"(c[1]), "+f"(c[2]), "+f"(c[3])
        : "r"(a0), "r"(a1), "r"(a2), "r"(a3), "r"(b0), "r"(b1));
}

__device__ __forceinline__ void ldsm4(uint32_t* r, uint32_t saddr) {
    asm volatile("ldmatrix.sync.aligned.m8n8.x4.shared.b16 {%0,%1,%2,%3}, [%4];"
        : "=r"(r[0]), "=r"(r[1]), "=r"(r[2]), "=r"(r[3]) : "r"(saddr));
}

__device__ __forceinline__ void cp16(uint32_t dst_smem, const void* src) {
    asm volatile("cp.async.cg.shared.global [%0], [%1], 16;"
        :: "r"(dst_smem), "l"(src));
}

// ---------------------------------------------------------------------------
// fused fp32 -> tf32 bits over all 6 tensors, 10 independent float4s/thread
// total float4s = 2*(XSZ/4) + 4*(WSZ/4) = 5242880 = 2048*256*10 exactly
// ---------------------------------------------------------------------------
#define XF (XSZ / 4)   // 2097152
#define WF (WSZ / 4)   // 262144

__global__ __launch_bounds__(256) void cvt_all(
    const float* __restrict__ x,  const float* __restrict__ ctx,
    const float* __restrict__ Wq, const float* __restrict__ Wk,
    const float* __restrict__ Wv, const float* __restrict__ Wo,
    uint32_t* __restrict__ xc, uint32_t* __restrict__ cc,
    uint32_t* __restrict__ wq, uint32_t* __restrict__ wk,
    uint32_t* __restrict__ wv, uint32_t* __restrict__ wo)
{
    const int base = blockIdx.x * 256 + threadIdx.x;
#pragma unroll
    for (int it = 0; it < 10; it++) {
        const int i = base + it * (2048 * 256);
        const float4* src;
        uint4* dst;
        int off;
        if (i < XF)            { src = (const float4*)x;   dst = (uint4*)xc; off = i; }
        else if (i < 2 * XF)   { src = (const float4*)ctx; dst = (uint4*)cc; off = i - XF; }
        else {
            const int j = i - 2 * XF;
            const int w = j >> 18;         // j / WF
            off = j & (WF - 1);
            switch (w) {
                case 0:  src = (const float4*)Wq; dst = (uint4*)wq; break;
                case 1:  src = (const float4*)Wk; dst = (uint4*)wk; break;
                case 2:  src = (const float4*)Wv; dst = (uint4*)wv; break;
                default: src = (const float4*)Wo; dst = (uint4*)wo; break;
            }
        }
        const float4 v = src[off];
        dst[off] = make_uint4(f2t(v.x), f2t(v.y), f2t(v.z), f2t(v.w));
    }
}

// ---------------------------------------------------------------------------
// TF32 GEMM body (pre-converted operands), 128x128x32, cp.async 2-stage
// ---------------------------------------------------------------------------
#define ASP 36
#define BSP 136
#define A_WORDS (128 * ASP)
#define B_WORDS (32 * BSP)
#define GEMM_SMEM_BYTES (2 * (A_WORDS + B_WORDS) * 4)

__device__ __forceinline__ void gemm_body(
    const uint32_t* __restrict__ A, const uint32_t* __restrict__ W,
    const float* __restrict__ bias, void* __restrict__ Cv,
    int obits, float oscale, uint32_t* smg)
{
    uint32_t* Bs = smg + 2 * A_WORDS;

    const int tid  = threadIdx.x;
    const int lane = tid & 31;
    const int wid  = tid >> 5;
    const int g    = lane >> 2;
    const int tig  = lane & 3;
    const int wm   = wid & 1;
    const int wn   = wid >> 1;
    const int row0 = blockIdx.y * 128;
    const int col0 = blockIdx.x * 128;

    const int arow = lane & 15;
    const int acol = (lane >> 4) * 4;
    const uint32_t As_base = (uint32_t)__cvta_generic_to_shared(smg);
    const uint32_t Bs_base = (uint32_t)__cvta_generic_to_shared(Bs);

    const int far = tid >> 3;
    const int fak = (tid & 7) * 4;
    const int fbk = tid >> 5;
    const int fbn = (tid & 31) * 4;

    float acc[4][4][4];
#pragma unroll
    for (int mi = 0; mi < 4; mi++)
#pragma unroll
        for (int ni = 0; ni < 4; ni++)
#pragma unroll
            for (int r = 0; r < 4; r++) acc[mi][ni][r] = 0.f;

    auto fill = [&](int s, int kt) {
        const uint32_t ab = As_base + s * A_WORDS * 4;
        const uint32_t bb = Bs_base + s * B_WORDS * 4;
#pragma unroll
        for (int i = 0; i < 4; i++) {
            const int r = far + i * 32;
            cp16(ab + (r * ASP + fak) * 4,
                 A + (size_t)(row0 + r) * 1024 + kt + fak);
        }
#pragma unroll
        for (int i = 0; i < 4; i++) {
            const int k = fbk + i * 8;
            cp16(bb + (k * BSP + fbn) * 4,
                 W + (size_t)(kt + k) * 1024 + col0 + fbn);
        }
        asm volatile("cp.async.commit_group;");
    };

    fill(0, 0);

    for (int t = 0; t < 32; t++) {
        const int cur = t & 1;
        if (t + 1 < 32) {
            fill(cur ^ 1, (t + 1) * 32);
            asm volatile("cp.async.wait_group 1;");
        } else {
            asm volatile("cp.async.wait_group 0;");
        }
        __syncthreads();

        const uint32_t ab = As_base + cur * A_WORDS * 4;
        const uint32_t* Bb = Bs + cur * B_WORDS;

#pragma unroll
        for (int kk = 0; kk < 32; kk += 8) {
            uint32_t af[4][4];
#pragma unroll
            for (int mi = 0; mi < 4; mi++) {
                const int m0 = wm * 64 + mi * 16;
                ldsm4(af[mi], ab + ((m0 + arow) * ASP + acol + kk) * 4);
            }
#pragma unroll
            for (int ni = 0; ni < 4; ni++) {
                const int n0 = wn * 32 + ni * 8;
                const uint32_t b0 = Bb[(kk + tig)     * BSP + n0 + g];
                const uint32_t b1 = Bb[(kk + tig + 4) * BSP + n0 + g];
#pragma unroll
                for (int mi = 0; mi < 4; mi++)
                    mma8(acc[mi][ni], af[mi][0], af[mi][1], af[mi][2], af[mi][3], b0, b1);
            }
        }
        __syncthreads();
    }

    if (obits) {
        uint32_t* Cb = (uint32_t*)Cv;
#pragma unroll
        for (int mi = 0; mi < 4; mi++) {
            const int rA = row0 + wm * 64 + mi * 16 + g;
#pragma unroll
            for (int ni = 0; ni < 4; ni++) {
                const int col = col0 + wn * 32 + ni * 8 + 2 * tig;
                *reinterpret_cast<uint2*>(&Cb[(size_t)rA * 1024 + col]) =
                    make_uint2(f2t(acc[mi][ni][0] * oscale), f2t(acc[mi][ni][1] * oscale));
                *reinterpret_cast<uint2*>(&Cb[(size_t)(rA + 8) * 1024 + col]) =
                    make_uint2(f2t(acc[mi][ni][2] * oscale), f2t(acc[mi][ni][3] * oscale));
            }
        }
    } else {
        float* Cf = (float*)Cv;
#pragma unroll
        for (int mi = 0; mi < 4; mi++) {
            const int rA = row0 + wm * 64 + mi * 16 + g;
#pragma unroll
            for (int ni = 0; ni < 4; ni++) {
                const int col = col0 + wn * 32 + ni * 8 + 2 * tig;
                const float b0v = bias[col], b1v = bias[col + 1];
                *reinterpret_cast<float2*>(&Cf[(size_t)rA * 1024 + col]) =
                    make_float2(acc[mi][ni][0] + b0v, acc[mi][ni][1] + b1v);
                *reinterpret_cast<float2*>(&Cf[(size_t)(rA + 8) * 1024 + col]) =
                    make_float2(acc[mi][ni][2] + b0v, acc[mi][ni][3] + b1v);
            }
        }
    }
}

// fused Q/K/V projection: blockIdx.z selects the GEMM
__global__ __launch_bounds__(256) void gemm_qkv(
    const uint32_t* __restrict__ xc, const uint32_t* __restrict__ cc,
    const uint32_t* __restrict__ wq, const uint32_t* __restrict__ wk,
    const uint32_t* __restrict__ wv,
    uint32_t* __restrict__ Qp, uint32_t* __restrict__ Kp,
    uint32_t* __restrict__ Vp)
{
    extern __shared__ uint32_t smg[];
    const int z = blockIdx.z;
    const uint32_t* A = (z == 0) ? xc : cc;
    const uint32_t* W = (z == 0) ? wq : (z == 1) ? wk : wv;
    uint32_t* C       = (z == 0) ? Qp : (z == 1) ? Kp : Vp;
    const float osc   = (z == 0) ? SCALE : 1.0f;
    gemm_body(A, W, nullptr, C, 1, osc, smg);
}

// single GEMM (final projection)
__global__ __launch_bounds__(256) void gemm_tf32(
    const uint32_t* __restrict__ A, const uint32_t* __restrict__ W,
    const float* __restrict__ bias, void* __restrict__ Cv,
    int obits, float oscale)
{
    extern __shared__ uint32_t smg[];
    gemm_body(A, W, bias, Cv, obits, oscale, smg);
}

// ---------------------------------------------------------------------------
// TF32 flash attention (R10-best): 128 queries/CTA, 8 warps x 16 rows,
// P-in-registers via sigma=(0,2,4,6,1,3,5,7), double-buffered K/V, 2 CTAs/SM
// ---------------------------------------------------------------------------
#define QSP 68
#define KVW (64 * QSP)
#define ATT_SMEM_BYTES ((128 * QSP + 4 * KVW) * 4 + 768)

__global__ __launch_bounds__(256, 2) void attn_tc(
    const uint32_t* __restrict__ Q, const uint32_t* __restrict__ K,
    const uint32_t* __restrict__ V, const int* __restrict__ mask,
    uint32_t* __restrict__ AO)
{
    extern __shared__ uint32_t sm[];
    uint32_t* Qs = sm;
    uint32_t* Ks = Qs + 128 * QSP;
    uint32_t* Vs = Ks + 2 * KVW;
    int*      msk = (int*)(Vs + 2 * KVW);

    const int tid  = threadIdx.x;
    const int lane = tid & 31;
    const int wid  = tid >> 5;
    const int g    = lane >> 2;
    const int tig  = lane & 3;
    const int n0   = blockIdx.x * 128;
    const int h    = blockIdx.y;
    const int b    = blockIdx.z;
    const int q0   = wid * 16;

    const int arow = lane & 15;
    const int acol = (lane >> 4) * 4;
    const int krow = (lane & 7) + ((lane >> 4) << 3);
    const int kcol = (lane & 8) ? 4 : 0;
    const uint32_t Qs_b = (uint32_t)__cvta_generic_to_shared(Qs);
    const uint32_t Ks_b = (uint32_t)__cvta_generic_to_shared(Ks);
    const uint32_t Vs_b = (uint32_t)__cvta_generic_to_shared(Vs);

    const int fr  = tid >> 4;
    const int fd4 = (tid & 15) * 4;

    auto fillKV = [&](int j0, int s) {
        const uint32_t kb = Ks_b + s * KVW * 4;
        const uint32_t vb = Vs_b + s * KVW * 4;
#pragma unroll
        for (int i = 0; i < 4; i++) {
            const int r = fr + i * 16;
            const size_t gb = ((size_t)b * MM + j0 + r) * IDD + h * 64 + fd4;
            cp16(kb + (r * QSP + fd4) * 4, K + gb);
            cp16(vb + (r * QSP + fd4) * 4, V + gb);
        }
        asm volatile("cp.async.commit_group;");
    };

#pragma unroll
    for (int i = 0; i < 8; i++) {
        const int r = fr + i * 16;
        cp16(Qs_b + (r * QSP + fd4) * 4,
             Q + ((size_t)b * NN + n0 + r) * IDD + h * 64 + fd4);
    }
    if (tid < 64) msk[tid] = mask[(size_t)b * MM + tid];
    fillKV(0, 0);

    float o[8][4];
#pragma unroll
    for (int nf = 0; nf < 8; nf++)
#pragma unroll
        for (int r = 0; r < 4; r++) o[nf][r] = 0.f;
    float mA = MAXNEG, mB = MAXNEG, lA = 0.f, lB = 0.f;

    for (int it = 0; it < 32; it++) {
        const int cur = it & 1;
        if (it + 1 < 32) {
            fillKV((it + 1) * 64, cur ^ 1);
            if (tid < 64)
                msk[(cur ^ 1) * 64 + tid] = mask[(size_t)b * MM + (it + 1) * 64 + tid];
            asm volatile("cp.async.wait_group 1;");
        } else {
            asm volatile("cp.async.wait_group 0;");
        }
        __syncthreads();

        const uint32_t kbb = Ks_b + cur * KVW * 4;
        const uint32_t* Vb = Vs + cur * KVW;
        const int* mk = msk + cur * 64;

        float s[8][4];
#pragma unroll
        for (int nf = 0; nf < 8; nf++)
#pragma unroll
            for (int r = 0; r < 4; r++) s[nf][r] = 0.f;

#pragma unroll
        for (int ks = 0; ks < 8; ks++) {
            const int d0 = ks * 8;
            uint32_t qa[4];
            ldsm4(qa, Qs_b + ((q0 + arow) * QSP + acol + d0) * 4);
#pragma unroll
            for (int np = 0; np < 4; np++) {
                const int jc = np * 16;
                uint32_t kb[4];
                ldsm4(kb, kbb + ((jc + krow) * QSP + kcol + d0) * 4);
                mma8(s[2*np],   qa[0], qa[1], qa[2], qa[3], kb[0], kb[1]);
                mma8(s[2*np+1], qa[0], qa[1], qa[2], qa[3], kb[2], kb[3]);
            }
        }

        float cmA = MAXNEG, cmB = MAXNEG;
#pragma unroll
        for (int nf = 0; nf < 8; nf++) {
            const int c0 = nf * 8 + 2 * tig;
            if (!mk[c0])     { s[nf][0] = MAXNEG; s[nf][2] = MAXNEG; }
            if (!mk[c0 + 1]) { s[nf][1] = MAXNEG; s[nf][3] = MAXNEG; }
            cmA = fmaxf(cmA, fmaxf(s[nf][0], s[nf][1]));
            cmB = fmaxf(cmB, fmaxf(s[nf][2], s[nf][3]));
        }
        cmA = fmaxf(cmA, __shfl_xor_sync(0xffffffffu, cmA, 1));
        cmA = fmaxf(cmA, __shfl_xor_sync(0xffffffffu, cmA, 2));
        cmB = fmaxf(cmB, __shfl_xor_sync(0xffffffffu, cmB, 1));
        cmB = fmaxf(cmB, __shfl_xor_sync(0xffffffffu, cmB, 2));

        const float mnA = fmaxf(mA, cmA);
        const float mnB = fmaxf(mB, cmB);
        const float alA = __expf(mA - mnA);
        const float alB = __expf(mB - mnB);
        mA = mnA; mB = mnB;

        float suA = 0.f, suB = 0.f;
#pragma unroll
        for (int nf = 0; nf < 8; nf++) {
            s[nf][0] = __expf(s[nf][0] - mnA);
            s[nf][1] = __expf(s[nf][1] - mnA);
            s[nf][2] = __expf(s[nf][2] - mnB);
            s[nf][3] = __expf(s[nf][3] - mnB);
            suA += s[nf][0] + s[nf][1];
            suB += s[nf][2] + s[nf][3];
        }
        suA += __shfl_xor_sync(0xffffffffu, suA, 1);
        suA += __shfl_xor_sync(0xffffffffu, suA, 2);
        suB += __shfl_xor_sync(0xffffffffu, suB, 1);
        suB += __shfl_xor_sync(0xffffffffu, suB, 2);
        lA = lA * alA + suA;
        lB = lB * alB + suB;

#pragma unroll
        for (int nf = 0; nf < 8; nf++) {
            o[nf][0] *= alA; o[nf][1] *= alA;
            o[nf][2] *= alB; o[nf][3] *= alB;
        }

#pragma unroll
        for (int ks = 0; ks < 8; ks++) {
            const int s0 = ks * 8;
            const uint32_t pa0 = f2t(s[ks][0]);
            const uint32_t pa1 = f2t(s[ks][2]);
            const uint32_t pa2 = f2t(s[ks][1]);
            const uint32_t pa3 = f2t(s[ks][3]);
#pragma unroll
            for (int nf = 0; nf < 8; nf++) {
                const int d0 = nf * 8;
                const uint32_t b0 = Vb[(s0 + 2 * tig)     * QSP + d0 + g];
                const uint32_t b1 = Vb[(s0 + 2 * tig + 1) * QSP + d0 + g];
                mma8(o[nf], pa0, pa1, pa2, pa3, b0, b1);
            }
        }
        __syncthreads();
    }

    const float liA = 1.f / lA;
    const float liB = 1.f / lB;
#pragma unroll
    for (int nf = 0; nf < 8; nf++) {
        const int col = h * 64 + nf * 8 + 2 * tig;
        const size_t rA = ((size_t)b * NN + n0 + q0 + g)     * IDD + col;
        const size_t rB = ((size_t)b * NN + n0 + q0 + g + 8) * IDD + col;
        *reinterpret_cast<uint2*>(&AO[rA]) =
            make_uint2(f2t(o[nf][0] * liA), f2t(o[nf][1] * liA));
        *reinterpret_cast<uint2*>(&AO[rB]) =
            make_uint2(f2t(o[nf][2] * liB), f2t(o[nf][3] * liB));
    }
}

// ---------------------------------------------------------------------------
// Launch
// ---------------------------------------------------------------------------
extern "C" void kernel_launch(void* const* d_in, const int* in_sizes, int n_in,
                              void* d_out, int out_size)
{
    const float* x    = (const float*)d_in[0];
    const float* ctx  = (const float*)d_in[1];
    const int*   mask = (const int*)d_in[2];
    const float* Wq   = (const float*)d_in[3];
    const float* Wk   = (const float*)d_in[4];
    const float* Wv   = (const float*)d_in[5];
    const float* Wo   = (const float*)d_in[6];
    const float* bo   = (const float*)d_in[7];
    float* out        = (float*)d_out;

    uint32_t *Qp, *Kp, *Vp, *AOp, *xc, *cc, *wq, *wk, *wv, *wo;
    cudaGetSymbolAddress((void**)&Qp,  g_Q);
    cudaGetSymbolAddress((void**)&Kp,  g_K);
    cudaGetSymbolAddress((void**)&Vp,  g_V);
    cudaGetSymbolAddress((void**)&AOp, g_AO);
    cudaGetSymbolAddress((void**)&xc,  g_xc);
    cudaGetSymbolAddress((void**)&cc,  g_cc);
    cudaGetSymbolAddress((void**)&wq,  g_wq);
    cudaGetSymbolAddress((void**)&wk,  g_wk);
    cudaGetSymbolAddress((void**)&wv,  g_wv);
    cudaGetSymbolAddress((void**)&wo,  g_wo);

    cudaFuncSetAttribute(attn_tc,
                         cudaFuncAttributeMaxDynamicSharedMemorySize,
                         ATT_SMEM_BYTES);
    cudaFuncSetAttribute(gemm_qkv,
                         cudaFuncAttributeMaxDynamicSharedMemorySize,
                         GEMM_SMEM_BYTES);
    cudaFuncSetAttribute(gemm_tf32,
                         cudaFuncAttributeMaxDynamicSharedMemorySize,
                         GEMM_SMEM_BYTES);

    cvt_all<<<2048, 256>>>(x, ctx, Wq, Wk, Wv, Wo, xc, cc, wq, wk, wv, wo);

    gemm_qkv<<<dim3(8, 64, 3), 256, GEMM_SMEM_BYTES>>>(
        xc, cc, wq, wk, wv, Qp, Kp, Vp);

    attn_tc<<<dim3(NN / 128, HH, BB), 256, ATT_SMEM_BYTES>>>(
        Qp, Kp, Vp, mask, AOp);

    gemm_tf32<<<dim3(8, 64), 256, GEMM_SMEM_BYTES>>>(AOp, wo, bo, out, 0, 1.0f);
}